// round 1
// baseline (speedup 1.0000x reference)
#include <cuda_runtime.h>

#define NB 16
#define NL 64
#define ND 256
#define NR 8
#define NBL (NB*NL)     // 1024
#define NP (NR*ND)      // 2048

// Scratch (device globals — no runtime allocation allowed)
__device__ float g_x [NBL*ND];        // gathered embeddings      [1024,256]
__device__ float g_io[NBL*3*ND];      // in_proj: shift|scale|px  [1024,768]
__device__ float g_p [NBL*NP];        // LN'd neighbor proj       [1024,2048]
__device__ float g_h [NBL*ND];        // recurrent state y        [1024,256]
__device__ int   g_len[NB];

// ---------- packed fp32x2 helpers ----------
__device__ __forceinline__ unsigned long long pack2(float v){
    unsigned long long r;
    asm("mov.b64 %0, {%1, %1};" : "=l"(r) : "f"(v));
    return r;
}
__device__ __forceinline__ float2 unpack2(unsigned long long v){
    float2 r;
    asm("mov.b64 {%0, %1}, %2;" : "=f"(r.x), "=f"(r.y) : "l"(v));
    return r;
}
__device__ __forceinline__ void ffma2(unsigned long long& d, unsigned long long a, unsigned long long b){
    asm("fma.rn.f32x2 %0, %1, %2, %0;" : "+l"(d) : "l"(a), "l"(b));
}

// ---------- prologue ----------
__global__ void gather_init_kernel(const int* __restrict__ tokens,
                                   const float* __restrict__ emb){
    int row = blockIdx.x;            // b*64 + l
    int b = row >> 6, l = row & 63;
    int tok = tokens[l*NB + b];      // tokens layout [L,B]
    int t = threadIdx.x;
    g_x[row*ND + t] = emb[tok*ND + t];
    g_h[row*ND + t] = 0.f;
}

__global__ void length_kernel(const int* __restrict__ tokens){
    int b = threadIdx.x;
    if (b < NB){
        int c = 0;
        for (int l = 0; l < NL; l++) c += (tokens[l*NB + b] != 0);
        g_len[b] = c;
    }
}

// ---------- tiled GEMM (M=1024, K=256), BM=64, BN=256, BK=16 ----------
// out[m][n] = sum_k H[m][k]*W[k][n] + bias[n]; optional LN over each 256-col group
template<bool DO_LN>
__global__ void __launch_bounds__(256) gemm_kernel(const float* __restrict__ H,
        const float* __restrict__ W, const float* __restrict__ bias,
        float* __restrict__ out, int N)
{
    __shared__ __align__(16) unsigned long long Hs2[16][64]; // A frag pre-duplicated for f32x2
    __shared__ __align__(16) float Ws[16][256];
    const int t  = threadIdx.x;
    const int tx = t & 31, ty = t >> 5;           // warp = ty; lanes span the 256 cols
    const int m0 = blockIdx.x * 64, n0 = blockIdx.y * 256;

    unsigned long long acc[8][4];
    #pragma unroll
    for (int i = 0; i < 8; i++)
        #pragma unroll
        for (int j = 0; j < 4; j++) acc[i][j] = 0ull;

    const int lm  = t & 63;            // H loader: row within tile
    const int lk  = (t >> 6) * 4;      // H loader: 4 consecutive k
    const int ln4 = (t & 63) * 4;      // W loader: 4 consecutive n
    const int lkr = (t >> 6) * 4;      // W loader: 4 k-rows

    for (int k0 = 0; k0 < 256; k0 += 16){
        float4 hv = *(const float4*)(H + (m0+lm)*ND + k0 + lk);
        Hs2[lk+0][lm] = pack2(hv.x);
        Hs2[lk+1][lm] = pack2(hv.y);
        Hs2[lk+2][lm] = pack2(hv.z);
        Hs2[lk+3][lm] = pack2(hv.w);
        #pragma unroll
        for (int q = 0; q < 4; q++){
            float4 wv = *(const float4*)(W + (k0+lkr+q)*N + n0 + ln4);
            *(float4*)&Ws[lkr+q][ln4] = wv;
        }
        __syncthreads();
        #pragma unroll
        for (int k = 0; k < 16; k++){
            const ulonglong2* ap = (const ulonglong2*)&Hs2[k][ty*8];
            ulonglong2 a01 = ap[0], a23 = ap[1], a45 = ap[2], a67 = ap[3];
            const ulonglong2* bp2 = (const ulonglong2*)&Ws[k][tx*8];
            ulonglong2 b01 = bp2[0], b23 = bp2[1];
            unsigned long long a2[8] = {a01.x,a01.y,a23.x,a23.y,a45.x,a45.y,a67.x,a67.y};
            unsigned long long b2[4] = {b01.x,b01.y,b23.x,b23.y};
            #pragma unroll
            for (int i = 0; i < 8; i++)
                #pragma unroll
                for (int j = 0; j < 4; j++)
                    ffma2(acc[i][j], a2[i], b2[j]);
        }
        __syncthreads();
    }

    float bja[8];
    #pragma unroll
    for (int j = 0; j < 8; j++) bja[j] = bias[n0 + tx*8 + j];

    #pragma unroll
    for (int i = 0; i < 8; i++){
        float v[8];
        #pragma unroll
        for (int j = 0; j < 4; j++){
            float2 u = unpack2(acc[i][j]);
            v[2*j]   = u.x + bja[2*j];
            v[2*j+1] = u.y + bja[2*j+1];
        }
        if (DO_LN){
            // two-pass LN over the 256 cols of this row (spread across the warp)
            float s = 0.f;
            #pragma unroll
            for (int j = 0; j < 8; j++) s += v[j];
            #pragma unroll
            for (int o = 16; o > 0; o >>= 1) s += __shfl_xor_sync(0xffffffffu, s, o);
            float mean = s * (1.f/256.f);
            float q = 0.f;
            #pragma unroll
            for (int j = 0; j < 8; j++){ float d = v[j]-mean; q += d*d; }
            #pragma unroll
            for (int o = 16; o > 0; o >>= 1) q += __shfl_xor_sync(0xffffffffu, q, o);
            float r = rsqrtf(q * (1.f/256.f) + 1e-5f);
            #pragma unroll
            for (int j = 0; j < 8; j++) v[j] = (v[j]-mean)*r;
        }
        float* op = out + (m0 + ty*8 + i)*N + n0 + tx*8;
        #pragma unroll
        for (int j = 0; j < 4; j++){
            float2 o2; o2.x = v[2*j]; o2.y = v[2*j+1];
            *(float2*)(op + 2*j) = o2;
        }
    }
}

// ---------- fused step: einsum + shrink + LN/gate + out-GEMM + tanh + mask ----------
// block handles (b, 8 consecutive j); grid = 128
__global__ void __launch_bounds__(256) step_kernel(
    const float* __restrict__ A, const float* __restrict__ Wout,
    const float* __restrict__ bout, int iter)
{
    __shared__ __align__(16) union USm {
        unsigned long long As2[512][8];                         // 32 KB (phase 1)
        struct { float ls[2][8][256]; float hsm[256][10]; } p2; // 26 KB (phases 2/3)
    } sm;

    const int t  = threadIdx.x;
    const int b  = blockIdx.x >> 3;
    const int j0 = (blockIdx.x & 7) * 8;
    const int row0 = b*64 + j0;

    // stage A column block: As2[k=i*8+h][jj] = A[b, i, j0+jj, h], pre-dup for f32x2
    const float* Ab = A + b*32768 + j0*8;
    #pragma unroll
    for (int idx = 0; idx < 16; idx++){
        int e = idx*256 + t;
        int k = e >> 3, jj = e & 7;
        float a = Ab[(k >> 3)*512 + jj*8 + (k & 7)];
        sm.As2[k][jj] = pack2(a);
    }
    __syncthreads();

    // phase 1: lin_sum[jj][d] = sum_k A[k][jj] * p[b,k,d]; k split over ty halves
    const int tx = t & 127;          // d-pair
    const int ty = t >> 7;           // k half
    unsigned long long acc[8];
    #pragma unroll
    for (int jj = 0; jj < 8; jj++) acc[jj] = 0ull;
    const float* pbase = g_p + (b*512 + ty*256)*256 + tx*2;
    #pragma unroll 4
    for (int k = 0; k < 256; k++){
        unsigned long long pv = *(const unsigned long long*)(pbase + k*256);
        int ks = ty*256 + k;
        #pragma unroll
        for (int jj = 0; jj < 8; jj++) ffma2(acc[jj], sm.As2[ks][jj], pv);
    }
    __syncthreads();   // all As2 reads complete before union is reused
    #pragma unroll
    for (int jj = 0; jj < 8; jj++){
        float2 u = unpack2(acc[jj]);
        sm.p2.ls[ty][jj][2*tx]   = u.x;
        sm.p2.ls[ty][jj][2*tx+1] = u.y;
    }
    __syncthreads();

    // phase 2: shrink + proj_x + LN + gate; warp r owns row j0+r
    const int r = t >> 5, lane = t & 31;
    const int row = row0 + r;
    const float* iorow = g_io + row*768;   // [0:256)=shift [256:512)=scale [512:768)=proj_x
    float hv[8];
    float s = 0.f;
    #pragma unroll
    for (int qq = 0; qq < 8; qq++){
        int d = qq*32 + lane;
        float x = sm.p2.ls[0][r][d] + sm.p2.ls[1][r][d];
        x = x - tanhf(x);              // shrink (accurate tanh: cancellation near 0)
        x += iorow[512 + d];           // + proj_x
        hv[qq] = x;
        s += x;
    }
    #pragma unroll
    for (int o = 16; o > 0; o >>= 1) s += __shfl_xor_sync(0xffffffffu, s, o);
    float mean = s * (1.f/256.f);
    float q = 0.f;
    #pragma unroll
    for (int qq = 0; qq < 8; qq++){ float d = hv[qq]-mean; q += d*d; }
    #pragma unroll
    for (int o = 16; o > 0; o >>= 1) q += __shfl_xor_sync(0xffffffffu, q, o);
    float rr = rsqrtf(q * (1.f/256.f) + 1e-5f);
    #pragma unroll
    for (int qq = 0; qq < 8; qq++){
        int d = qq*32 + lane;
        float lnv = (hv[qq]-mean)*rr;
        float g = fmaf(iorow[d], lnv, iorow[256+d]);   // shift*ln + scale
        sm.p2.hsm[d][r] = fmaxf(g, 0.f);               // relu -> h
    }
    __syncthreads();

    // phase 3: y[r][n] = tanh( sum_k h[r][k]*Wout[k][n] + bout[n] ), rows paired for f32x2
    unsigned long long yacc[4] = {0ull, 0ull, 0ull, 0ull};
    #pragma unroll 4
    for (int k = 0; k < 256; k++){
        unsigned long long w2 = pack2(Wout[k*256 + t]);
        const unsigned long long* hp = (const unsigned long long*)&sm.p2.hsm[k][0];
        ffma2(yacc[0], hp[0], w2);
        ffma2(yacc[1], hp[1], w2);
        ffma2(yacc[2], hp[2], w2);
        ffma2(yacc[3], hp[3], w2);
    }
    float bo = bout[t];
    bool masked = (iter > g_len[b]);
    #pragma unroll
    for (int qq = 0; qq < 4; qq++){
        float2 u = unpack2(yacc[qq]);
        float y0 = masked ? 0.f : tanhf(u.x + bo);
        float y1 = masked ? 0.f : tanhf(u.y + bo);
        g_h[(row0 + 2*qq    )*256 + t] = y0;
        g_h[(row0 + 2*qq + 1)*256 + t] = y1;
    }
}

// ---------- epilogue: final[b][d] = sum_i h[b,i,d]*root[b,i] ----------
__global__ void finalize_kernel(const float* __restrict__ root, float* __restrict__ out){
    int b = blockIdx.x, t = threadIdx.x;
    float s = 0.f;
    #pragma unroll 8
    for (int i = 0; i < 64; i++)
        s += g_h[(b*64 + i)*256 + t] * root[b*64 + i];
    out[b*256 + t] = s;
}

extern "C" void kernel_launch(void* const* d_in, const int* in_sizes, int n_in,
                              void* d_out, int out_size)
{
    const int*   tokens = (const int*)  d_in[0];
    const float* A      = (const float*)d_in[1];
    const float* root   = (const float*)d_in[2];
    const float* emb    = (const float*)d_in[3];
    const float* Wp     = (const float*)d_in[4];
    const float* bp     = (const float*)d_in[5];
    const float* Win    = (const float*)d_in[6];
    const float* bin    = (const float*)d_in[7];
    const float* Wout   = (const float*)d_in[8];
    const float* bout   = (const float*)d_in[9];
    float* out = (float*)d_out;

    float *px, *pio, *pp, *ph;
    cudaGetSymbolAddress((void**)&px,  g_x);
    cudaGetSymbolAddress((void**)&pio, g_io);
    cudaGetSymbolAddress((void**)&pp,  g_p);
    cudaGetSymbolAddress((void**)&ph,  g_h);

    gather_init_kernel<<<NBL, ND>>>(tokens, emb);
    length_kernel<<<1, NB>>>(tokens);
    gemm_kernel<false><<<dim3(16, 3), 256>>>(px, Win, bin, pio, 768);   // hoisted in_proj

    for (int it = 0; it < 64; it++){
        int i = 64 - it;                                                // i = L..1
        gemm_kernel<true><<<dim3(16, 8), 256>>>(ph, Wp, bp, pp, 2048);  // p = LN(h@Wp + bp)
        step_kernel<<<128, 256>>>(A, Wout, bout, i);                    // einsum..mask -> h
    }

    finalize_kernel<<<16, 256>>>(root, out);
}